// round 13
// baseline (speedup 1.0000x reference)
#include <cuda_runtime.h>
#include <cuda_fp16.h>
#include <cstdint>

#define NVOX   (2*96*96*64)   // 1179648
#define TPB    128
#define VPC    256            // voxels per CTA
#define NCTA   (NVOX / VPC)   // 4608
#define KCOMP  16

// B fragments: [kstep 2][ntile 64][lane 32] uint2 (f16 Linv/20).
// ntile nt, col p (=lane>>2): comp c = 4*(nt&3) + (p>>1), dim d = 2*(nt>>2) + (p&1)
static __device__ uint2  g_Bfrag[2 * 64 * 32];
static __device__ float2 g_bfrag[64 * 4];   // [ntile][colpair] = -b/20
static __device__ float  g_a2[KCOMP];

// ---------------- helpers ---------------------------------------------------
__device__ __forceinline__ uint32_t smem_u32(const void* p) {
    uint32_t a;
    asm("{ .reg .u64 t; cvta.to.shared.u64 t, %1; cvt.u32.u64 %0, t; }"
        : "=r"(a) : "l"(p));
    return a;
}
__device__ __forceinline__ void ldm4(uint32_t* r, uint32_t addr) {
    asm volatile("ldmatrix.sync.aligned.m8n8.x4.shared.b16 {%0,%1,%2,%3}, [%4];"
        : "=r"(r[0]), "=r"(r[1]), "=r"(r[2]), "=r"(r[3]) : "r"(addr));
}
__device__ __forceinline__ void mma16816(float* d, const uint32_t* a,
                                         const uint32_t* b, const float* c) {
    asm volatile("mma.sync.aligned.m16n8k16.row.col.f32.f16.f16.f32 "
        "{%0,%1,%2,%3}, {%4,%5,%6,%7}, {%8,%9}, {%10,%11,%12,%13};"
        : "=f"(d[0]), "=f"(d[1]), "=f"(d[2]), "=f"(d[3])
        : "r"(a[0]), "r"(a[1]), "r"(a[2]), "r"(a[3]),
          "r"(b[0]), "r"(b[1]),
          "f"(c[0]), "f"(c[1]), "f"(c[2]), "f"(c[3]));
}

// packed smem addressing: voxel v, 16B-chunk c (0..3)
__device__ __forceinline__ uint32_t zaddr(uint32_t Zb, uint32_t v, uint32_t c) {
    return Zb + (v >> 1) * 128u + (v & 1u) * 64u + (((c ^ (v >> 1)) & 3u) << 4);
}

// ---------------- prep: 16 blocks (one per component) x 128 threads ---------
__global__ void __launch_bounds__(128)
prep_kernel(const float* __restrict__ wbg,  const float* __restrict__ mubg,
            const float* __restrict__ Lbg,  const float* __restrict__ wfg,
            const float* __restrict__ mufg, const float* __restrict__ Lfg) {
    __shared__ float sL[528];
    __shared__ float sT[528];
    __shared__ float sb[32];
    int kc = blockIdx.x;
    int tid = threadIdx.x;
    const float* L  = (kc < 8) ? (Lbg  + kc * 1024) : (Lfg  + (kc - 8) * 1024);
    const float* mu = (kc < 8) ? (mubg + kc * 32)   : (mufg + (kc - 8) * 32);

    for (int e = tid; e < 528; e += 128) {
        int i = (int)((sqrtf(8.0f * e + 1.0f) - 1.0f) * 0.5f);
        while ((i + 1) * (i + 2) / 2 <= e) ++i;
        while (i * (i + 1) / 2 > e) --i;
        int j = e - i * (i + 1) / 2;
        sL[e] = L[i * 32 + j];
    }
    __syncthreads();

    if (tid < 32) {
        int j = tid;
        float vv[32];
#pragma unroll
        for (int r = 0; r < 32; ++r) {
            float s = 0.0f;
#pragma unroll
            for (int m = 0; m < r; ++m) s += sL[r * (r + 1) / 2 + m] * vv[m];
            float d = sL[r * (r + 1) / 2 + r];
            vv[r] = (r < j) ? 0.0f : ((r == j) ? 1.0f / d : -s / d);
        }
#pragma unroll
        for (int r = 0; r < 32; ++r)
            if (r >= j) sT[r * (r + 1) / 2 + j] = vv[r];
        __syncwarp();
        float bj = 0.0f;
        for (int c = 0; c <= j; ++c) bj += sT[j * (j + 1) / 2 + c] * mu[c];
        sb[j] = bj;
        float lg = logf(sL[j * (j + 1) / 2 + j]);
#pragma unroll
        for (int off = 16; off > 0; off >>= 1)
            lg += __shfl_xor_sync(0xFFFFFFFFu, lg, off);
        if (j == 0) {
            float wk = (kc < 8) ? wbg[kc] : wfg[kc - 8];
            const float cst = -0.5f * 32.0f * 1.8378770664093453f;
            g_a2[kc] = wk * expf((cst - lg) * 0.005f);
        }
    }
    __syncthreads();

    int qc = kc & 3, ac = kc >> 2;
    for (int idx = tid; idx < 256; idx += 128) {
        int s  = idx >> 7;
        int j  = (idx >> 3) & 15;
        int pl = idx & 7;
        int p  = 2 * qc + (pl >> 2);
        int kq = pl & 3;
        int lane = p * 4 + kq;
        int nt = 4 * j + ac;
        int d  = 2 * j + (p & 1);
        int k0 = 16 * s + kq * 2;
        const float* row = sT + d * (d + 1) / 2;
        float v0 = (k0     <= d) ? row[k0]     * 0.05f : 0.0f;
        float v1 = (k0 + 1 <= d) ? row[k0 + 1] * 0.05f : 0.0f;
        float v2 = (k0 + 8 <= d) ? row[k0 + 8] * 0.05f : 0.0f;
        float v3 = (k0 + 9 <= d) ? row[k0 + 9] * 0.05f : 0.0f;
        __half2 lo = __floats2half2_rn(v0, v1);
        __half2 hi = __floats2half2_rn(v2, v3);
        uint2 u;
        u.x = *(uint32_t*)&lo;
        u.y = *(uint32_t*)&hi;
        g_Bfrag[(s * 64 + nt) * 32 + lane] = u;
    }
    if (tid < 16) {
        int j = tid;
        int nt = 4 * j + ac;
        int d0 = 2 * j;
        g_bfrag[nt * 4 + qc] = make_float2(-sb[d0] * 0.05f, -sb[d0 + 1] * 0.05f);
    }
}

// ---------------- density: M=64/warp whitening GEMM -------------------------
__global__ void __launch_bounds__(TPB, 6)
density_kernel(const float* __restrict__ fm, float* __restrict__ out) {
    __shared__ __align__(128) char sZ[16384];   // 256 voxels x 64B packed

    int tid = threadIdx.x;
    int lane = tid & 31;
    int wid = tid >> 5;
    size_t v0 = (size_t)blockIdx.x * VPC;
    uint32_t Zb = smem_u32(sZ);

    // coalesced load + f16 convert + packed scatter (conflict-free STS.64)
    {
        const float4* xf = (const float4*)(fm + v0 * 32);
#pragma unroll
        for (int i = 0; i < 16; ++i) {
            int g = i * TPB + tid;
            float4 t4 = xf[g];
            __half2 lo = __floats2half2_rn(t4.x, t4.y);
            __half2 hi = __floats2half2_rn(t4.z, t4.w);
            uint32_t ul = *(uint32_t*)&lo, uh = *(uint32_t*)&hi;
            uint32_t v = (uint32_t)(g >> 3);
            uint32_t pos = (uint32_t)(g & 7);
            uint32_t addr = zaddr(Zb, v, pos >> 1) + (pos & 1u) * 8u;
            asm volatile("st.shared.v2.b32 [%0], {%1, %2};"
                         :: "r"(addr), "r"(ul), "r"(uh) : "memory");
        }
    }
    __syncthreads();

    // A fragments: 4 m-tiles x 2 ksteps
    uint32_t colsel = (uint32_t)(lane >> 4);
    uint32_t vrow = (uint32_t)(wid * 64 + (lane & 7) + ((lane >> 3) & 1) * 8);
    uint32_t A[4][2][4];
#pragma unroll
    for (int mt = 0; mt < 4; ++mt) {
        uint32_t v = vrow + mt * 16;
#pragma unroll
        for (int s = 0; s < 2; ++s)
            ldm4(A[mt][s], zaddr(Zb, v, (uint32_t)(s * 2) + colsel));
    }

    const uint2*  __restrict__ gB = g_Bfrag;
    const float2* __restrict__ gb = g_bfrag;
    int q3 = lane & 3;

    float dens[8];
#pragma unroll
    for (int i = 0; i < 8; ++i) dens[i] = 0.0f;

#pragma unroll
    for (int a = 0; a < 4; ++a) {
        // scalar f32 square-sum accumulators, one per output row (8 rows)
        float e2[8];
#pragma unroll
        for (int i = 0; i < 8; ++i) e2[i] = 0.0f;
#pragma unroll
        for (int j = 0; j < 16; ++j) {
            int nt = 4 * j + a;
            uint2 b0 = __ldg(&gB[nt * 32 + lane]);
            float2 bi = __ldg(&gb[nt * 4 + q3]);
            uint2 b1;
            if (j >= 8) b1 = __ldg(&gB[(64 + nt) * 32 + lane]);
#pragma unroll
            for (int mt = 0; mt < 4; ++mt) {
                float acc[4] = {bi.x, bi.y, bi.x, bi.y};
                mma16816(acc, A[mt][0], (uint32_t*)&b0, acc);
                if (j >= 8) mma16816(acc, A[mt][1], (uint32_t*)&b1, acc);
                e2[mt * 2]     = fmaf(acc[0], acc[0],
                                 fmaf(acc[1], acc[1], e2[mt * 2]));
                e2[mt * 2 + 1] = fmaf(acc[2], acc[2],
                                 fmaf(acc[3], acc[3], e2[mt * 2 + 1]));
            }
        }
        float ac = __ldg(&g_a2[4 * a + q3]);
#pragma unroll
        for (int i = 0; i < 8; ++i)
            dens[i] += ac * __expf(-e2[i]);
    }

    // reduce over the 4 colpair lanes, store
#pragma unroll
    for (int i = 0; i < 8; ++i) {
        float d = dens[i];
        d += __shfl_xor_sync(0xFFFFFFFFu, d, 1);
        d += __shfl_xor_sync(0xFFFFFFFFu, d, 2);
        if (q3 == 0) {
            int mt = i >> 1, h = i & 1;
            size_t r = v0 + (size_t)(wid * 64 + mt * 16 + h * 8 + (lane >> 2));
            out[r] = ((r & 63) == 63) ? 0.0f : d;
        }
    }
}

// ---------------- launch ----------------------------------------------------
extern "C" void kernel_launch(void* const* d_in, const int* in_sizes, int n_in,
                              void* d_out, int out_size) {
    const float* fm   = (const float*)d_in[0];
    const float* wbg  = (const float*)d_in[1];
    const float* mubg = (const float*)d_in[2];
    const float* Lbg  = (const float*)d_in[3];
    const float* wfg  = (const float*)d_in[4];
    const float* mufg = (const float*)d_in[5];
    const float* Lfg  = (const float*)d_in[6];
    float* out = (float*)d_out;

    prep_kernel<<<KCOMP, 128>>>(wbg, mubg, Lbg, wfg, mufg, Lfg);
    density_kernel<<<NCTA, TPB>>>(fm, out);
}

// round 15
// speedup vs baseline: 1.0176x; 1.0176x over previous
#include <cuda_runtime.h>
#include <cuda_fp16.h>
#include <cstdint>

#define NVOX   (2*96*96*64)   // 1179648
#define TPB    128
#define VPC    256            // voxels per CTA
#define NCTA   (NVOX / VPC)   // 4608
#define KCOMP  16

// B fragments: [kstep 2][ntile 64][lane 32] uint2 (f16 Linv/20).
// ntile nt, col p (=lane>>2): comp c = 4*(nt&3) + (p>>1), dim d = 2*(nt>>2) + (p&1)
static __device__ uint2  g_Bfrag[2 * 64 * 32];
static __device__ float2 g_bfrag[64 * 4];   // [ntile][colpair] = -b/20
static __device__ float  g_a2[KCOMP];

// ---------------- helpers ---------------------------------------------------
__device__ __forceinline__ uint32_t smem_u32(const void* p) {
    uint32_t a;
    asm("{ .reg .u64 t; cvta.to.shared.u64 t, %1; cvt.u32.u64 %0, t; }"
        : "=r"(a) : "l"(p));
    return a;
}
__device__ __forceinline__ void ldm4(uint32_t* r, uint32_t addr) {
    asm volatile("ldmatrix.sync.aligned.m8n8.x4.shared.b16 {%0,%1,%2,%3}, [%4];"
        : "=r"(r[0]), "=r"(r[1]), "=r"(r[2]), "=r"(r[3]) : "r"(addr));
}
__device__ __forceinline__ void mma16816(float* d, const uint32_t* a,
                                         const uint32_t* b, const float* c) {
    asm volatile("mma.sync.aligned.m16n8k16.row.col.f32.f16.f16.f32 "
        "{%0,%1,%2,%3}, {%4,%5,%6,%7}, {%8,%9}, {%10,%11,%12,%13};"
        : "=f"(d[0]), "=f"(d[1]), "=f"(d[2]), "=f"(d[3])
        : "r"(a[0]), "r"(a[1]), "r"(a[2]), "r"(a[3]),
          "r"(b[0]), "r"(b[1]),
          "f"(c[0]), "f"(c[1]), "f"(c[2]), "f"(c[3]));
}

// packed smem addressing: voxel v, 16B-chunk c (0..3)
__device__ __forceinline__ uint32_t zaddr(uint32_t Zb, uint32_t v, uint32_t c) {
    return Zb + (v >> 1) * 128u + (v & 1u) * 64u + (((c ^ (v >> 1)) & 3u) << 4);
}

// ---------------- prep: 16 blocks (one per component) x 128 threads ---------
__global__ void __launch_bounds__(128)
prep_kernel(const float* __restrict__ wbg,  const float* __restrict__ mubg,
            const float* __restrict__ Lbg,  const float* __restrict__ wfg,
            const float* __restrict__ mufg, const float* __restrict__ Lfg) {
    __shared__ float sL[528];
    __shared__ float sT[528];
    __shared__ float sb[32];
    int kc = blockIdx.x;
    int tid = threadIdx.x;
    const float* L  = (kc < 8) ? (Lbg  + kc * 1024) : (Lfg  + (kc - 8) * 1024);
    const float* mu = (kc < 8) ? (mubg + kc * 32)   : (mufg + (kc - 8) * 32);

    for (int e = tid; e < 528; e += 128) {
        int i = (int)((sqrtf(8.0f * e + 1.0f) - 1.0f) * 0.5f);
        while ((i + 1) * (i + 2) / 2 <= e) ++i;
        while (i * (i + 1) / 2 > e) --i;
        int j = e - i * (i + 1) / 2;
        sL[e] = L[i * 32 + j];
    }
    __syncthreads();

    if (tid < 32) {
        int j = tid;
        float vv[32];
#pragma unroll
        for (int r = 0; r < 32; ++r) {
            float s = 0.0f;
#pragma unroll
            for (int m = 0; m < r; ++m) s += sL[r * (r + 1) / 2 + m] * vv[m];
            float d = sL[r * (r + 1) / 2 + r];
            vv[r] = (r < j) ? 0.0f : ((r == j) ? 1.0f / d : -s / d);
        }
#pragma unroll
        for (int r = 0; r < 32; ++r)
            if (r >= j) sT[r * (r + 1) / 2 + j] = vv[r];
        __syncwarp();
        float bj = 0.0f;
        for (int c = 0; c <= j; ++c) bj += sT[j * (j + 1) / 2 + c] * mu[c];
        sb[j] = bj;
        float lg = logf(sL[j * (j + 1) / 2 + j]);
#pragma unroll
        for (int off = 16; off > 0; off >>= 1)
            lg += __shfl_xor_sync(0xFFFFFFFFu, lg, off);
        if (j == 0) {
            float wk = (kc < 8) ? wbg[kc] : wfg[kc - 8];
            const float cst = -0.5f * 32.0f * 1.8378770664093453f;
            g_a2[kc] = wk * expf((cst - lg) * 0.005f);
        }
    }
    __syncthreads();

    int qc = kc & 3, ac = kc >> 2;
    for (int idx = tid; idx < 256; idx += 128) {
        int s  = idx >> 7;
        int j  = (idx >> 3) & 15;
        int pl = idx & 7;
        int p  = 2 * qc + (pl >> 2);
        int kq = pl & 3;
        int lane = p * 4 + kq;
        int nt = 4 * j + ac;
        int d  = 2 * j + (p & 1);
        int k0 = 16 * s + kq * 2;
        const float* row = sT + d * (d + 1) / 2;
        float v0 = (k0     <= d) ? row[k0]     * 0.05f : 0.0f;
        float v1 = (k0 + 1 <= d) ? row[k0 + 1] * 0.05f : 0.0f;
        float v2 = (k0 + 8 <= d) ? row[k0 + 8] * 0.05f : 0.0f;
        float v3 = (k0 + 9 <= d) ? row[k0 + 9] * 0.05f : 0.0f;
        __half2 lo = __floats2half2_rn(v0, v1);
        __half2 hi = __floats2half2_rn(v2, v3);
        uint2 u;
        u.x = *(uint32_t*)&lo;
        u.y = *(uint32_t*)&hi;
        g_Bfrag[(s * 64 + nt) * 32 + lane] = u;
    }
    if (tid < 16) {
        int j = tid;
        int nt = 4 * j + ac;
        int d0 = 2 * j;
        g_bfrag[nt * 4 + qc] = make_float2(-sb[d0] * 0.05f, -sb[d0 + 1] * 0.05f);
    }
}

// ---------------- density: M=64/warp whitening GEMM -------------------------
__global__ void __launch_bounds__(TPB, 5)
density_kernel(const float* __restrict__ fm, float* __restrict__ out) {
    __shared__ __align__(128) char sZ[16384];   // 256 voxels x 64B packed

    int tid = threadIdx.x;
    int lane = tid & 31;
    int wid = tid >> 5;
    size_t v0 = (size_t)blockIdx.x * VPC;
    uint32_t Zb = smem_u32(sZ);

    // coalesced load + f16 convert + packed scatter (conflict-free STS.64)
    {
        const float4* xf = (const float4*)(fm + v0 * 32);
#pragma unroll
        for (int i = 0; i < 16; ++i) {
            int g = i * TPB + tid;
            float4 t4 = xf[g];
            __half2 lo = __floats2half2_rn(t4.x, t4.y);
            __half2 hi = __floats2half2_rn(t4.z, t4.w);
            uint32_t ul = *(uint32_t*)&lo, uh = *(uint32_t*)&hi;
            uint32_t v = (uint32_t)(g >> 3);
            uint32_t pos = (uint32_t)(g & 7);
            uint32_t addr = zaddr(Zb, v, pos >> 1) + (pos & 1u) * 8u;
            asm volatile("st.shared.v2.b32 [%0], {%1, %2};"
                         :: "r"(addr), "r"(ul), "r"(uh) : "memory");
        }
    }
    __syncthreads();

    // A fragments: 4 m-tiles x 2 ksteps
    uint32_t colsel = (uint32_t)(lane >> 4);
    uint32_t vrow = (uint32_t)(wid * 64 + (lane & 7) + ((lane >> 3) & 1) * 8);
    uint32_t A[4][2][4];
#pragma unroll
    for (int mt = 0; mt < 4; ++mt) {
        uint32_t v = vrow + mt * 16;
#pragma unroll
        for (int s = 0; s < 2; ++s)
            ldm4(A[mt][s], zaddr(Zb, v, (uint32_t)(s * 2) + colsel));
    }

    const uint2*  __restrict__ gB = g_Bfrag;
    const float2* __restrict__ gb = g_bfrag;
    int q3 = lane & 3;

    float dens[8];
#pragma unroll
    for (int i = 0; i < 8; ++i) dens[i] = 0.0f;

#pragma unroll
    for (int a = 0; a < 4; ++a) {
        // scalar f32 square-sum accumulators, one per output row (8 rows)
        float e2[8];
#pragma unroll
        for (int i = 0; i < 8; ++i) e2[i] = 0.0f;
#pragma unroll
        for (int j = 0; j < 16; ++j) {
            int nt = 4 * j + a;
            uint2 b0 = __ldg(&gB[nt * 32 + lane]);
            float2 bi = __ldg(&gb[nt * 4 + q3]);
            uint2 b1;
            if (j >= 8) b1 = __ldg(&gB[(64 + nt) * 32 + lane]);
#pragma unroll
            for (int mt = 0; mt < 4; ++mt) {
                float acc[4] = {bi.x, bi.y, bi.x, bi.y};
                mma16816(acc, A[mt][0], (uint32_t*)&b0, acc);
                if (j >= 8) mma16816(acc, A[mt][1], (uint32_t*)&b1, acc);
                e2[mt * 2]     = fmaf(acc[0], acc[0],
                                 fmaf(acc[1], acc[1], e2[mt * 2]));
                e2[mt * 2 + 1] = fmaf(acc[2], acc[2],
                                 fmaf(acc[3], acc[3], e2[mt * 2 + 1]));
            }
        }
        float ac = __ldg(&g_a2[4 * a + q3]);
#pragma unroll
        for (int i = 0; i < 8; ++i)
            dens[i] += ac * __expf(-e2[i]);
    }

    // reduce over the 4 colpair lanes, store
#pragma unroll
    for (int i = 0; i < 8; ++i) {
        float d = dens[i];
        d += __shfl_xor_sync(0xFFFFFFFFu, d, 1);
        d += __shfl_xor_sync(0xFFFFFFFFu, d, 2);
        if (q3 == 0) {
            int mt = i >> 1, h = i & 1;
            size_t r = v0 + (size_t)(wid * 64 + mt * 16 + h * 8 + (lane >> 2));
            out[r] = ((r & 63) == 63) ? 0.0f : d;
        }
    }
}

// ---------------- launch ----------------------------------------------------
extern "C" void kernel_launch(void* const* d_in, const int* in_sizes, int n_in,
                              void* d_out, int out_size) {
    const float* fm   = (const float*)d_in[0];
    const float* wbg  = (const float*)d_in[1];
    const float* mubg = (const float*)d_in[2];
    const float* Lbg  = (const float*)d_in[3];
    const float* wfg  = (const float*)d_in[4];
    const float* mufg = (const float*)d_in[5];
    const float* Lfg  = (const float*)d_in[6];
    float* out = (float*)d_out;

    prep_kernel<<<KCOMP, 128>>>(wbg, mubg, Lbg, wfg, mufg, Lfg);
    density_kernel<<<NCTA, TPB>>>(fm, out);
}

// round 17
// speedup vs baseline: 1.2115x; 1.1905x over previous
#include <cuda_runtime.h>
#include <cuda_fp16.h>
#include <cstdint>

#define NVOX   (2*96*96*64)   // 1179648
#define TPB    128
#define VPC    256            // voxels per CTA
#define NCTA   (NVOX / VPC)   // 4608
#define KCOMP  16

// B fragments: [kstep 2][ntile 64][lane 32] uint2 (f16 Linv/20).
// ntile nt, col p (=lane>>2): comp c = 4*(nt&3) + (p>>1), dim d = 2*(nt>>2) + (p&1)
static __device__ uint2    g_Bfrag[2 * 64 * 32];
static __device__ uint32_t g_bfragh[64 * 4];  // [ntile][colpair] half2(-b/20)
static __device__ float    g_a2[KCOMP];

// ---------------- helpers ---------------------------------------------------
__device__ __forceinline__ uint32_t smem_u32(const void* p) {
    uint32_t a;
    asm("{ .reg .u64 t; cvta.to.shared.u64 t, %1; cvt.u32.u64 %0, t; }"
        : "=r"(a) : "l"(p));
    return a;
}
__device__ __forceinline__ void ldm4(uint32_t* r, uint32_t addr) {
    asm volatile("ldmatrix.sync.aligned.m8n8.x4.shared.b16 {%0,%1,%2,%3}, [%4];"
        : "=r"(r[0]), "=r"(r[1]), "=r"(r[2]), "=r"(r[3]) : "r"(addr));
}
// f16-accumulate mma: D (2 regs, f16x2) = A*B + C
__device__ __forceinline__ void mma16816h(uint32_t* d, const uint32_t* a,
                                          const uint32_t* b,
                                          uint32_t c0, uint32_t c1) {
    asm volatile("mma.sync.aligned.m16n8k16.row.col.f16.f16.f16.f16 "
        "{%0,%1}, {%2,%3,%4,%5}, {%6,%7}, {%8,%9};"
        : "=r"(d[0]), "=r"(d[1])
        : "r"(a[0]), "r"(a[1]), "r"(a[2]), "r"(a[3]),
          "r"(b[0]), "r"(b[1]), "r"(c0), "r"(c1));
}
__device__ __forceinline__ uint32_t hfma2u(uint32_t a, uint32_t b, uint32_t c) {
    uint32_t d;
    asm("fma.rn.f16x2 %0, %1, %2, %3;" : "=r"(d) : "r"(a), "r"(b), "r"(c));
    return d;
}

// packed smem addressing: voxel v, 16B-chunk c (0..3)
__device__ __forceinline__ uint32_t zaddr(uint32_t Zb, uint32_t v, uint32_t c) {
    return Zb + (v >> 1) * 128u + (v & 1u) * 64u + (((c ^ (v >> 1)) & 3u) << 4);
}

// ---------------- prep: 16 blocks (one per component) x 128 threads ---------
__global__ void __launch_bounds__(128)
prep_kernel(const float* __restrict__ wbg,  const float* __restrict__ mubg,
            const float* __restrict__ Lbg,  const float* __restrict__ wfg,
            const float* __restrict__ mufg, const float* __restrict__ Lfg) {
    __shared__ float sL[528];
    __shared__ float sT[528];
    __shared__ float sb[32];
    int kc = blockIdx.x;
    int tid = threadIdx.x;
    const float* L  = (kc < 8) ? (Lbg  + kc * 1024) : (Lfg  + (kc - 8) * 1024);
    const float* mu = (kc < 8) ? (mubg + kc * 32)   : (mufg + (kc - 8) * 32);

    for (int e = tid; e < 528; e += 128) {
        int i = (int)((sqrtf(8.0f * e + 1.0f) - 1.0f) * 0.5f);
        while ((i + 1) * (i + 2) / 2 <= e) ++i;
        while (i * (i + 1) / 2 > e) --i;
        int j = e - i * (i + 1) / 2;
        sL[e] = L[i * 32 + j];
    }
    __syncthreads();

    if (tid < 32) {
        int j = tid;
        float vv[32];
#pragma unroll
        for (int r = 0; r < 32; ++r) {
            float s = 0.0f;
#pragma unroll
            for (int m = 0; m < r; ++m) s += sL[r * (r + 1) / 2 + m] * vv[m];
            float d = sL[r * (r + 1) / 2 + r];
            vv[r] = (r < j) ? 0.0f : ((r == j) ? 1.0f / d : -s / d);
        }
#pragma unroll
        for (int r = 0; r < 32; ++r)
            if (r >= j) sT[r * (r + 1) / 2 + j] = vv[r];
        __syncwarp();
        float bj = 0.0f;
        for (int c = 0; c <= j; ++c) bj += sT[j * (j + 1) / 2 + c] * mu[c];
        sb[j] = bj;
        float lg = logf(sL[j * (j + 1) / 2 + j]);
#pragma unroll
        for (int off = 16; off > 0; off >>= 1)
            lg += __shfl_xor_sync(0xFFFFFFFFu, lg, off);
        if (j == 0) {
            float wk = (kc < 8) ? wbg[kc] : wfg[kc - 8];
            const float cst = -0.5f * 32.0f * 1.8378770664093453f;
            g_a2[kc] = wk * expf((cst - lg) * 0.005f);
        }
    }
    __syncthreads();

    int qc = kc & 3, ac = kc >> 2;
    for (int idx = tid; idx < 256; idx += 128) {
        int s  = idx >> 7;
        int j  = (idx >> 3) & 15;
        int pl = idx & 7;
        int p  = 2 * qc + (pl >> 2);
        int kq = pl & 3;
        int lane = p * 4 + kq;
        int nt = 4 * j + ac;
        int d  = 2 * j + (p & 1);
        int k0 = 16 * s + kq * 2;
        const float* row = sT + d * (d + 1) / 2;
        float v0 = (k0     <= d) ? row[k0]     * 0.05f : 0.0f;
        float v1 = (k0 + 1 <= d) ? row[k0 + 1] * 0.05f : 0.0f;
        float v2 = (k0 + 8 <= d) ? row[k0 + 8] * 0.05f : 0.0f;
        float v3 = (k0 + 9 <= d) ? row[k0 + 9] * 0.05f : 0.0f;
        __half2 lo = __floats2half2_rn(v0, v1);
        __half2 hi = __floats2half2_rn(v2, v3);
        uint2 u;
        u.x = *(uint32_t*)&lo;
        u.y = *(uint32_t*)&hi;
        g_Bfrag[(s * 64 + nt) * 32 + lane] = u;
    }
    if (tid < 16) {
        int j = tid;
        int nt = 4 * j + ac;
        int d0 = 2 * j;
        __half2 bh = __floats2half2_rn(-sb[d0] * 0.05f, -sb[d0 + 1] * 0.05f);
        g_bfragh[nt * 4 + qc] = *(uint32_t*)&bh;
    }
}

// ---------------- density: M=64/warp whitening GEMM, f16-acc HMMA -----------
__global__ void __launch_bounds__(TPB)
density_kernel(const float* __restrict__ fm, float* __restrict__ out) {
    __shared__ __align__(128) char sZ[16384];   // 256 voxels x 64B packed

    int tid = threadIdx.x;
    int lane = tid & 31;
    int wid = tid >> 5;
    size_t v0 = (size_t)blockIdx.x * VPC;
    uint32_t Zb = smem_u32(sZ);

    // coalesced load + f16 convert + packed scatter (conflict-free STS.64)
    {
        const float4* xf = (const float4*)(fm + v0 * 32);
#pragma unroll
        for (int i = 0; i < 16; ++i) {
            int g = i * TPB + tid;
            float4 t4 = xf[g];
            __half2 lo = __floats2half2_rn(t4.x, t4.y);
            __half2 hi = __floats2half2_rn(t4.z, t4.w);
            uint32_t ul = *(uint32_t*)&lo, uh = *(uint32_t*)&hi;
            uint32_t v = (uint32_t)(g >> 3);
            uint32_t pos = (uint32_t)(g & 7);
            uint32_t addr = zaddr(Zb, v, pos >> 1) + (pos & 1u) * 8u;
            asm volatile("st.shared.v2.b32 [%0], {%1, %2};"
                         :: "r"(addr), "r"(ul), "r"(uh) : "memory");
        }
    }
    __syncthreads();

    // A fragments: 4 m-tiles x 2 ksteps
    uint32_t colsel = (uint32_t)(lane >> 4);
    uint32_t vrow = (uint32_t)(wid * 64 + (lane & 7) + ((lane >> 3) & 1) * 8);
    uint32_t A[4][2][4];
#pragma unroll
    for (int mt = 0; mt < 4; ++mt) {
        uint32_t v = vrow + mt * 16;
#pragma unroll
        for (int s = 0; s < 2; ++s)
            ldm4(A[mt][s], zaddr(Zb, v, (uint32_t)(s * 2) + colsel));
    }

    const uint2*    __restrict__ gB = g_Bfrag;
    const uint32_t* __restrict__ gb = g_bfragh;
    int q3 = lane & 3;

    float dens[8];
#pragma unroll
    for (int i = 0; i < 8; ++i) dens[i] = 0.0f;

#pragma unroll
    for (int a = 0; a < 4; ++a) {
        // half2 square-sum accumulators (fed by f16 mma outputs; no CVT)
        uint32_t e2[8];
#pragma unroll
        for (int i = 0; i < 8; ++i) e2[i] = 0u;
#pragma unroll
        for (int j = 0; j < 16; ++j) {
            int nt = 4 * j + a;
            uint2 b0 = __ldg(&gB[nt * 32 + lane]);
            uint32_t bih = __ldg(&gb[nt * 4 + q3]);
            uint2 b1;
            if (j >= 8) b1 = __ldg(&gB[(64 + nt) * 32 + lane]);
#pragma unroll
            for (int mt = 0; mt < 4; ++mt) {
                uint32_t dh[2];
                mma16816h(dh, A[mt][0], (uint32_t*)&b0, bih, bih);
                if (j >= 8) mma16816h(dh, A[mt][1], (uint32_t*)&b1, dh[0], dh[1]);
                e2[mt * 2]     = hfma2u(dh[0], dh[0], e2[mt * 2]);
                e2[mt * 2 + 1] = hfma2u(dh[1], dh[1], e2[mt * 2 + 1]);
            }
        }
        float ac = __ldg(&g_a2[4 * a + q3]);
#pragma unroll
        for (int i = 0; i < 8; ++i) {
            float2 s2 = __half22float2(*(__half2*)&e2[i]);
            dens[i] += ac * __expf(-(s2.x + s2.y));
        }
    }

    // reduce over the 4 colpair lanes, store
#pragma unroll
    for (int i = 0; i < 8; ++i) {
        float d = dens[i];
        d += __shfl_xor_sync(0xFFFFFFFFu, d, 1);
        d += __shfl_xor_sync(0xFFFFFFFFu, d, 2);
        if (q3 == 0) {
            int mt = i >> 1, h = i & 1;
            size_t r = v0 + (size_t)(wid * 64 + mt * 16 + h * 8 + (lane >> 2));
            out[r] = ((r & 63) == 63) ? 0.0f : d;
        }
    }
}

// ---------------- launch ----------------------------------------------------
extern "C" void kernel_launch(void* const* d_in, const int* in_sizes, int n_in,
                              void* d_out, int out_size) {
    const float* fm   = (const float*)d_in[0];
    const float* wbg  = (const float*)d_in[1];
    const float* mubg = (const float*)d_in[2];
    const float* Lbg  = (const float*)d_in[3];
    const float* wfg  = (const float*)d_in[4];
    const float* mufg = (const float*)d_in[5];
    const float* Lfg  = (const float*)d_in[6];
    float* out = (float*)d_out;

    prep_kernel<<<KCOMP, 128>>>(wbg, mubg, Lbg, wfg, mufg, Lfg);
    density_kernel<<<NCTA, TPB>>>(fm, out);
}